// round 1
// baseline (speedup 1.0000x reference)
#include <cuda_runtime.h>
#include <math.h>

#define SEQ   1024
#define HEADS 12
#define BATCH 16
#define DH    64
#define DIM   768
#define BHT   (BATCH*HEADS)   // 192

// scratch for q,k,v in (which, b, h, s, c) layout: 3*192*1024*64 floats = 151 MB
__device__ float g_qkv[3UL * BHT * SEQ * DH];

// ---------------------------------------------------------------------------
// Kernel 1: qkv = x @ w^T + b  -> scattered into g_qkv[(which,bh,s,c)]
// C tile 128x128, BK=16, 256 threads, 8x8 register blocking.
// ---------------------------------------------------------------------------
__global__ __launch_bounds__(256) void qkv_gemm(const float* __restrict__ x,
                                                const float* __restrict__ w,
                                                const float* __restrict__ bq) {
    __shared__ float As[16][132];   // A^T tile  [k][m], padded
    __shared__ float Bs[16][132];   // B^T tile  [k][n], padded

    const int tid = threadIdx.x;
    const int m0  = blockIdx.y * 128;
    const int n0  = blockIdx.x * 128;
    const int ty  = tid >> 4;       // 0..15
    const int tx  = tid & 15;       // 0..15

    float acc[8][8];
#pragma unroll
    for (int i = 0; i < 8; i++)
#pragma unroll
        for (int j = 0; j < 8; j++) acc[i][j] = 0.f;

    const float* A  = x + (size_t)m0 * DIM;
    const float* Bp = w + (size_t)n0 * DIM;

    const int lr  = tid >> 2;        // 0..63 row within half-tile
    const int lc4 = (tid & 3) * 4;   // 0,4,8,12 (k-col group)

    for (int k0 = 0; k0 < DIM; k0 += 16) {
#pragma unroll
        for (int i = 0; i < 2; i++) {
            int r = lr + i * 64;
            float4 a4 = *(const float4*)(A + r * DIM + k0 + lc4);
            As[lc4 + 0][r] = a4.x; As[lc4 + 1][r] = a4.y;
            As[lc4 + 2][r] = a4.z; As[lc4 + 3][r] = a4.w;
            float4 b4 = *(const float4*)(Bp + r * DIM + k0 + lc4);
            Bs[lc4 + 0][r] = b4.x; Bs[lc4 + 1][r] = b4.y;
            Bs[lc4 + 2][r] = b4.z; Bs[lc4 + 3][r] = b4.w;
        }
        __syncthreads();
#pragma unroll
        for (int k = 0; k < 16; k++) {
            float ra[8], rb[8];
            *(float4*)(ra)     = *(const float4*)&As[k][ty * 8];
            *(float4*)(ra + 4) = *(const float4*)&As[k][ty * 8 + 4];
            *(float4*)(rb)     = *(const float4*)&Bs[k][tx * 8];
            *(float4*)(rb + 4) = *(const float4*)&Bs[k][tx * 8 + 4];
#pragma unroll
            for (int i = 0; i < 8; i++)
#pragma unroll
                for (int j = 0; j < 8; j++)
                    acc[i][j] += ra[i] * rb[j];
        }
        __syncthreads();
    }

    // epilogue: scatter into (which, b, h, s, c) layout
    const int nb    = n0 + tx * 8;       // 8 consecutive output cols, same which & head
    const int which = nb / DIM;
    const int hn    = nb % DIM;
    const int h     = hn >> 6;
    const int c0    = hn & 63;

    float bb[8];
#pragma unroll
    for (int j = 0; j < 8; j++) bb[j] = bq[nb + j];

#pragma unroll
    for (int i = 0; i < 8; i++) {
        int m = m0 + ty * 8 + i;
        int b = m >> 10;
        int s = m & 1023;
        float* dst = g_qkv + ((size_t)(which * BHT + b * HEADS + h) * SEQ + s) * DH + c0;
        float4 v0 = make_float4(acc[i][0] + bb[0], acc[i][1] + bb[1],
                                acc[i][2] + bb[2], acc[i][3] + bb[3]);
        float4 v1 = make_float4(acc[i][4] + bb[4], acc[i][5] + bb[5],
                                acc[i][6] + bb[6], acc[i][7] + bb[7]);
        *(float4*)(dst)     = v0;
        *(float4*)(dst + 4) = v1;
    }
}

// ---------------------------------------------------------------------------
// Kernel 2: flash-style attention, fp32.
// One CTA = one (b,h) pair x 64 query rows. 256 threads (16x16), 4x4 frags.
// Qs/Ks stored transposed [c][i] (stride 68) -> conflict-free float4 reads.
// ---------------------------------------------------------------------------
#define ATS   68
#define AT_SMEM (4 * 64 * ATS * (int)sizeof(float))   // Qs,Ks,Vs,Ps = 69632 B

__global__ __launch_bounds__(256) void attn_kernel(const float* __restrict__ dsc,
                                                   const float* __restrict__ bias,
                                                   float* __restrict__ out) {
    extern __shared__ float smf[];
    float* Qs = smf;                 // [64][68] transposed: Qs[c][i]
    float* Ks = smf + 64 * ATS;      // [64][68] transposed: Ks[c][j]
    float* Vs = smf + 2 * 64 * ATS;  // [64][68] natural:    Vs[j][c]
    float* Ps = smf + 3 * 64 * ATS;  // [64][68] natural:    Ps[i][j]

    const int tid = threadIdx.x;
    const int ty  = tid >> 4;      // 0..15 -> rows 4*ty..4*ty+3
    const int tx  = tid & 15;      // 0..15 -> cols 4*tx..4*tx+3
    const int bh  = blockIdx.y;
    const int q0  = blockIdx.x * 64;
    const int b   = bh / HEADS;
    const int h   = bh % HEADS;

    const float* qp = g_qkv + ((size_t)(0 * BHT + bh) * SEQ + q0) * DH;
    const float* kp = g_qkv + ((size_t)(1 * BHT + bh) * SEQ) * DH;
    const float* vp = g_qkv + ((size_t)(2 * BHT + bh) * SEQ) * DH;

    // load Q tile transposed
#pragma unroll
    for (int i = 0; i < 4; i++) {
        int idx = tid + i * 256;
        int r = idx >> 4;
        int c = (idx & 15) * 4;
        float4 a = *(const float4*)(qp + r * DH + c);
        Qs[(c + 0) * ATS + r] = a.x;
        Qs[(c + 1) * ATS + r] = a.y;
        Qs[(c + 2) * ATS + r] = a.z;
        Qs[(c + 3) * ATS + r] = a.w;
    }

    float m_i[4], l_i[4], acc[4][4];
#pragma unroll
    for (int i = 0; i < 4; i++) {
        m_i[i] = -1e30f; l_i[i] = 0.f;
#pragma unroll
        for (int j = 0; j < 4; j++) acc[i][j] = 0.f;
    }

    const float scale = 0.125f;  // 64^-0.5

    for (int t = 0; t < 16; t++) {
        const int k0c = t * 64;
        __syncthreads();  // guards Qs(1st iter) + Ks/Vs reuse from prev iter

        // load K tile transposed + V tile direct
#pragma unroll
        for (int i = 0; i < 4; i++) {
            int idx = tid + i * 256;
            int r = idx >> 4;
            int c = (idx & 15) * 4;
            float4 a = *(const float4*)(kp + (k0c + r) * DH + c);
            Ks[(c + 0) * ATS + r] = a.x;
            Ks[(c + 1) * ATS + r] = a.y;
            Ks[(c + 2) * ATS + r] = a.z;
            Ks[(c + 3) * ATS + r] = a.w;
            float4 v = *(const float4*)(vp + (k0c + r) * DH + c);
            *(float4*)(Vs + r * ATS + c) = v;
        }
        __syncthreads();

        // S = Q K^T (4x4 per thread)
        float s[4][4];
#pragma unroll
        for (int i = 0; i < 4; i++)
#pragma unroll
            for (int j = 0; j < 4; j++) s[i][j] = 0.f;

#pragma unroll 8
        for (int c = 0; c < 64; c++) {
            float4 q4 = *(const float4*)(Qs + c * ATS + ty * 4);
            float4 k4 = *(const float4*)(Ks + c * ATS + tx * 4);
            float qv[4] = {q4.x, q4.y, q4.z, q4.w};
            float kv[4] = {k4.x, k4.y, k4.z, k4.w};
#pragma unroll
            for (int i = 0; i < 4; i++)
#pragma unroll
                for (int j = 0; j < 4; j++)
                    s[i][j] += qv[i] * kv[j];
        }

        // scale + bias + online softmax
#pragma unroll
        for (int ii = 0; ii < 4; ii++) {
            int row = q0 + ty * 4 + ii;
            float4 b4 = *(const float4*)(bias + row * SEQ + k0c + tx * 4);
            s[ii][0] = s[ii][0] * scale + b4.x;
            s[ii][1] = s[ii][1] * scale + b4.y;
            s[ii][2] = s[ii][2] * scale + b4.z;
            s[ii][3] = s[ii][3] * scale + b4.w;

            float mt = fmaxf(fmaxf(s[ii][0], s[ii][1]), fmaxf(s[ii][2], s[ii][3]));
            mt = fmaxf(mt, __shfl_xor_sync(0xffffffffu, mt, 8));
            mt = fmaxf(mt, __shfl_xor_sync(0xffffffffu, mt, 4));
            mt = fmaxf(mt, __shfl_xor_sync(0xffffffffu, mt, 2));
            mt = fmaxf(mt, __shfl_xor_sync(0xffffffffu, mt, 1));

            float m_new = fmaxf(m_i[ii], mt);
            float fac   = __expf(m_i[ii] - m_new);
            m_i[ii] = m_new;

            float p0 = __expf(s[ii][0] - m_new);
            float p1 = __expf(s[ii][1] - m_new);
            float p2 = __expf(s[ii][2] - m_new);
            float p3 = __expf(s[ii][3] - m_new);
            float rs = p0 + p1 + p2 + p3;
            rs += __shfl_xor_sync(0xffffffffu, rs, 8);
            rs += __shfl_xor_sync(0xffffffffu, rs, 4);
            rs += __shfl_xor_sync(0xffffffffu, rs, 2);
            rs += __shfl_xor_sync(0xffffffffu, rs, 1);

            l_i[ii] = l_i[ii] * fac + rs;
#pragma unroll
            for (int j = 0; j < 4; j++) acc[ii][j] *= fac;

            *(float4*)(Ps + (ty * 4 + ii) * ATS + tx * 4) = make_float4(p0, p1, p2, p3);
        }
        __syncthreads();

        // O += P @ V
#pragma unroll 4
        for (int j = 0; j < 64; j++) {
            float4 v4 = *(const float4*)(Vs + j * ATS + tx * 4);
#pragma unroll
            for (int ii = 0; ii < 4; ii++) {
                float p = Ps[(ty * 4 + ii) * ATS + j];
                acc[ii][0] += p * v4.x;
                acc[ii][1] += p * v4.y;
                acc[ii][2] += p * v4.z;
                acc[ii][3] += p * v4.w;
            }
        }
    }

    // epilogue: out[b, row, h*64 + c] = d[row] * O / l
#pragma unroll
    for (int ii = 0; ii < 4; ii++) {
        int row = q0 + ty * 4 + ii;
        float sc = dsc[row] / l_i[ii];
        float4 o = make_float4(acc[ii][0] * sc, acc[ii][1] * sc,
                               acc[ii][2] * sc, acc[ii][3] * sc);
        *(float4*)(out + ((size_t)(b * SEQ + row) * DIM) + h * DH + tx * 4) = o;
    }
}

// ---------------------------------------------------------------------------
extern "C" void kernel_launch(void* const* d_in, const int* in_sizes, int n_in,
                              void* d_out, int out_size) {
    const float* x    = (const float*)d_in[0];
    const float* w    = (const float*)d_in[1];
    const float* bq   = (const float*)d_in[2];
    const float* dsc  = (const float*)d_in[3];
    const float* bias = (const float*)d_in[4];
    float* out = (float*)d_out;

    cudaFuncSetAttribute(attn_kernel, cudaFuncAttributeMaxDynamicSharedMemorySize, AT_SMEM);

    qkv_gemm<<<dim3(18, 128), 256>>>(x, w, bq);
    attn_kernel<<<dim3(16, BHT), 256, AT_SMEM>>>(dsc, bias, out);
}

// round 2
// speedup vs baseline: 2.5970x; 2.5970x over previous
#include <cuda_runtime.h>
#include <math.h>

#define SEQ   1024
#define HEADS 12
#define BATCH 16
#define DH    64
#define DIM   768
#define BHT   (BATCH*HEADS)   // 192

// scratch for q,k,v in (which, b*h, s, c) layout
__device__ float g_qkv[3UL * BHT * SEQ * DH];

__device__ __forceinline__ unsigned f2tf(float f) {
    unsigned r;
    asm("cvt.rna.tf32.f32 %0, %1;" : "=r"(r) : "f"(f));
    return r;
}

__device__ __forceinline__ void mma_tf32(float c[4], const unsigned a[4], const unsigned b[2]) {
    asm volatile("mma.sync.aligned.m16n8k8.row.col.f32.tf32.tf32.f32 "
                 "{%0,%1,%2,%3}, {%4,%5,%6,%7}, {%8,%9}, {%0,%1,%2,%3};"
                 : "+f"(c[0]), "+f"(c[1]), "+f"(c[2]), "+f"(c[3])
                 : "r"(a[0]), "r"(a[1]), "r"(a[2]), "r"(a[3]),
                   "r"(b[0]), "r"(b[1]));
}

// ---------------------------------------------------------------------------
// Kernel 1: qkv = x @ w^T + b  (tf32 tensor-core GEMM)
// C tile 128x128, BK=32, 8 warps, each warp 32x64 (2 m-tiles x 8 n-tiles).
// smem tiles stored row-major with stride 36 -> fragment loads conflict-free.
// ---------------------------------------------------------------------------
#define LDA 36

__global__ __launch_bounds__(256) void qkv_gemm(const float* __restrict__ x,
                                                const float* __restrict__ w,
                                                const float* __restrict__ bq) {
    __shared__ unsigned As[128 * LDA];
    __shared__ unsigned Bs[128 * LDA];

    const int tid  = threadIdx.x;
    const int warp = tid >> 5;
    const int lane = tid & 31;
    const int r0   = lane >> 2;   // 0..7
    const int qq   = lane & 3;    // 0..3
    const int wr   = warp >> 1;   // 0..3
    const int wc   = warp & 1;    // 0..1
    const int m_w  = wr * 32;
    const int n_w  = wc * 64;

    float C[2][8][4];
#pragma unroll
    for (int i = 0; i < 2; i++)
#pragma unroll
        for (int j = 0; j < 8; j++)
#pragma unroll
            for (int k = 0; k < 4; k++) C[i][j][k] = 0.f;

    const float* Ag = x + (size_t)(blockIdx.y * 128) * DIM;
    const float* Bg = w + (size_t)(blockIdx.x * 128) * DIM;

    for (int k0 = 0; k0 < DIM; k0 += 32) {
        __syncthreads();
#pragma unroll
        for (int i = 0; i < 4; i++) {
            int id = tid + i * 256;
            int r  = id >> 3;
            int c  = (id & 7) * 4;
            float4 a4 = *(const float4*)(Ag + (size_t)r * DIM + k0 + c);
            uint4  at = make_uint4(f2tf(a4.x), f2tf(a4.y), f2tf(a4.z), f2tf(a4.w));
            *(uint4*)&As[r * LDA + c] = at;
            float4 b4 = *(const float4*)(Bg + (size_t)r * DIM + k0 + c);
            uint4  bt = make_uint4(f2tf(b4.x), f2tf(b4.y), f2tf(b4.z), f2tf(b4.w));
            *(uint4*)&Bs[r * LDA + c] = bt;
        }
        __syncthreads();

#pragma unroll
        for (int ks = 0; ks < 4; ks++) {
            const int kk = ks * 8;
            unsigned a[2][4], b[8][2];
#pragma unroll
            for (int mt = 0; mt < 2; mt++) {
                int row = m_w + mt * 16;
                a[mt][0] = As[(row + r0) * LDA + kk + qq];
                a[mt][1] = As[(row + r0 + 8) * LDA + kk + qq];
                a[mt][2] = As[(row + r0) * LDA + kk + qq + 4];
                a[mt][3] = As[(row + r0 + 8) * LDA + kk + qq + 4];
            }
#pragma unroll
            for (int nt = 0; nt < 8; nt++) {
                int col = n_w + nt * 8;
                b[nt][0] = Bs[(col + r0) * LDA + kk + qq];
                b[nt][1] = Bs[(col + r0) * LDA + kk + qq + 4];
            }
#pragma unroll
            for (int mt = 0; mt < 2; mt++)
#pragma unroll
                for (int nt = 0; nt < 8; nt++)
                    mma_tf32(C[mt][nt], a[mt], b[nt]);
        }
    }

    // epilogue: add bias, scatter into (which, bh, s, c)
#pragma unroll
    for (int nt = 0; nt < 8; nt++) {
        int nb = blockIdx.x * 128 + n_w + nt * 8 + 2 * qq;
        float2 bb = *(const float2*)(bq + nb);
        int which = nb / DIM;
        int hn    = nb % DIM;
        int h     = hn >> 6;
        int c0    = hn & 63;
        size_t base = ((size_t)which * BHT) * SEQ * DH + (size_t)h * SEQ * DH + c0;
#pragma unroll
        for (int mt = 0; mt < 2; mt++) {
            int m = blockIdx.y * 128 + m_w + mt * 16 + r0;
            {
                int b = m >> 10, s = m & 1023;
                float* dst = g_qkv + base + ((size_t)b * HEADS * SEQ + s) * DH;
                *(float2*)dst = make_float2(C[mt][nt][0] + bb.x, C[mt][nt][1] + bb.y);
            }
            {
                int m2 = m + 8;
                int b = m2 >> 10, s = m2 & 1023;
                float* dst = g_qkv + base + ((size_t)b * HEADS * SEQ + s) * DH;
                *(float2*)dst = make_float2(C[mt][nt][2] + bb.x, C[mt][nt][3] + bb.y);
            }
        }
    }
}

// ---------------------------------------------------------------------------
// Kernel 2: flash attention, tf32 mma. BM=128 rows/CTA, BN=64 keys/iter.
// 8 warps; warp w owns rows 16w..16w+15 (full-row softmax in 4-lane shuffles).
// ---------------------------------------------------------------------------
#define QS   68   // Q / P / K smem stride
#define VS   72   // V smem stride
#define AT_SMEM ((128*QS + 64*QS + 64*VS + 128*QS) * 4)

__global__ __launch_bounds__(256) void attn_kernel(const float* __restrict__ dsc,
                                                   const float* __restrict__ bias,
                                                   float* __restrict__ out) {
    extern __shared__ unsigned smu[];
    unsigned* Qs = smu;
    unsigned* Ks = Qs + 128 * QS;
    unsigned* Vs = Ks + 64 * QS;
    unsigned* Ps = Vs + 64 * VS;

    const int tid  = threadIdx.x;
    const int warp = tid >> 5;
    const int lane = tid & 31;
    const int r0   = lane >> 2;
    const int qq   = lane & 3;
    const int wm   = warp * 16;

    const int bh = blockIdx.y;
    const int q0 = blockIdx.x * 128;
    const int b  = bh / HEADS;
    const int h  = bh % HEADS;

    const float* qp = g_qkv + ((size_t)(0 * BHT + bh) * SEQ + q0) * DH;
    const float* kp = g_qkv + ((size_t)(1 * BHT + bh) * SEQ) * DH;
    const float* vp = g_qkv + ((size_t)(2 * BHT + bh) * SEQ) * DH;

    // load Q tile (128x64) -> tf32 smem
#pragma unroll
    for (int i = 0; i < 8; i++) {
        int id = tid + i * 256;
        int r  = id >> 4;
        int c  = (id & 15) * 4;
        float4 a = *(const float4*)(qp + (size_t)r * DH + c);
        *(uint4*)&Qs[r * QS + c] = make_uint4(f2tf(a.x), f2tf(a.y), f2tf(a.z), f2tf(a.w));
    }

    float O[8][4];
#pragma unroll
    for (int i = 0; i < 8; i++)
#pragma unroll
        for (int j = 0; j < 4; j++) O[i][j] = 0.f;
    float m0 = -1e30f, m1 = -1e30f, l0 = 0.f, l1 = 0.f;

    const float scale = 0.125f;

    for (int t = 0; t < 16; t++) {
        __syncthreads();
        // load K,V tiles (64x64 each)
#pragma unroll
        for (int i = 0; i < 4; i++) {
            int id = tid + i * 256;
            int r  = id >> 4;
            int c  = (id & 15) * 4;
            float4 k4 = *(const float4*)(kp + (size_t)(t * 64 + r) * DH + c);
            *(uint4*)&Ks[r * QS + c] = make_uint4(f2tf(k4.x), f2tf(k4.y), f2tf(k4.z), f2tf(k4.w));
            float4 v4 = *(const float4*)(vp + (size_t)(t * 64 + r) * DH + c);
            *(uint4*)&Vs[r * VS + c] = make_uint4(f2tf(v4.x), f2tf(v4.y), f2tf(v4.z), f2tf(v4.w));
        }
        __syncthreads();

        // S = Q K^T  (warp: 16 x 64)
        float S[8][4];
#pragma unroll
        for (int i = 0; i < 8; i++)
#pragma unroll
            for (int j = 0; j < 4; j++) S[i][j] = 0.f;

#pragma unroll
        for (int ks = 0; ks < 8; ks++) {
            const int kk = ks * 8;
            unsigned a[4];
            a[0] = Qs[(wm + r0) * QS + kk + qq];
            a[1] = Qs[(wm + r0 + 8) * QS + kk + qq];
            a[2] = Qs[(wm + r0) * QS + kk + qq + 4];
            a[3] = Qs[(wm + r0 + 8) * QS + kk + qq + 4];
#pragma unroll
            for (int nt = 0; nt < 8; nt++) {
                unsigned bf[2];
                bf[0] = Ks[(nt * 8 + r0) * QS + kk + qq];
                bf[1] = Ks[(nt * 8 + r0) * QS + kk + qq + 4];
                mma_tf32(S[nt], a, bf);
            }
        }

        // scale + bias, online softmax (rows wm+r0 and wm+r0+8)
        const float* br0 = bias + (size_t)(q0 + wm + r0) * SEQ + t * 64;
        const float* br1 = br0 + 8 * SEQ;
        float mx0 = -1e30f, mx1 = -1e30f;
#pragma unroll
        for (int nt = 0; nt < 8; nt++) {
            float2 b0 = *(const float2*)(br0 + nt * 8 + 2 * qq);
            float2 b1 = *(const float2*)(br1 + nt * 8 + 2 * qq);
            S[nt][0] = S[nt][0] * scale + b0.x;
            S[nt][1] = S[nt][1] * scale + b0.y;
            S[nt][2] = S[nt][2] * scale + b1.x;
            S[nt][3] = S[nt][3] * scale + b1.y;
            mx0 = fmaxf(mx0, fmaxf(S[nt][0], S[nt][1]));
            mx1 = fmaxf(mx1, fmaxf(S[nt][2], S[nt][3]));
        }
        mx0 = fmaxf(mx0, __shfl_xor_sync(0xffffffffu, mx0, 1));
        mx0 = fmaxf(mx0, __shfl_xor_sync(0xffffffffu, mx0, 2));
        mx1 = fmaxf(mx1, __shfl_xor_sync(0xffffffffu, mx1, 1));
        mx1 = fmaxf(mx1, __shfl_xor_sync(0xffffffffu, mx1, 2));

        float mn0 = fmaxf(m0, mx0), mn1 = fmaxf(m1, mx1);
        float f0 = __expf(m0 - mn0), f1 = __expf(m1 - mn1);
        m0 = mn0; m1 = mn1;

        float rs0 = 0.f, rs1 = 0.f;
#pragma unroll
        for (int nt = 0; nt < 8; nt++) {
            float p0 = __expf(S[nt][0] - mn0);
            float p1 = __expf(S[nt][1] - mn0);
            float p2 = __expf(S[nt][2] - mn1);
            float p3 = __expf(S[nt][3] - mn1);
            rs0 += p0 + p1;
            rs1 += p2 + p3;
            Ps[(wm + r0) * QS + nt * 8 + 2 * qq]     = f2tf(p0);
            Ps[(wm + r0) * QS + nt * 8 + 2 * qq + 1] = f2tf(p1);
            Ps[(wm + r0 + 8) * QS + nt * 8 + 2 * qq]     = f2tf(p2);
            Ps[(wm + r0 + 8) * QS + nt * 8 + 2 * qq + 1] = f2tf(p3);
        }
        rs0 += __shfl_xor_sync(0xffffffffu, rs0, 1);
        rs0 += __shfl_xor_sync(0xffffffffu, rs0, 2);
        rs1 += __shfl_xor_sync(0xffffffffu, rs1, 1);
        rs1 += __shfl_xor_sync(0xffffffffu, rs1, 2);
        l0 = l0 * f0 + rs0;
        l1 = l1 * f1 + rs1;

#pragma unroll
        for (int nt = 0; nt < 8; nt++) {
            O[nt][0] *= f0; O[nt][1] *= f0;
            O[nt][2] *= f1; O[nt][3] *= f1;
        }
        __syncwarp();

        // O += P @ V  (P rows warp-private)
#pragma unroll
        for (int ks = 0; ks < 8; ks++) {
            const int kk = ks * 8;
            unsigned a[4];
            a[0] = Ps[(wm + r0) * QS + kk + qq];
            a[1] = Ps[(wm + r0 + 8) * QS + kk + qq];
            a[2] = Ps[(wm + r0) * QS + kk + qq + 4];
            a[3] = Ps[(wm + r0 + 8) * QS + kk + qq + 4];
#pragma unroll
            for (int nt = 0; nt < 8; nt++) {
                unsigned bf[2];
                bf[0] = Vs[(kk + qq) * VS + nt * 8 + r0];
                bf[1] = Vs[(kk + qq + 4) * VS + nt * 8 + r0];
                mma_tf32(O[nt], a, bf);
            }
        }
    }

    // epilogue
    {
        int row0 = q0 + wm + r0;
        int row1 = row0 + 8;
        float sc0 = dsc[row0] / l0;
        float sc1 = dsc[row1] / l1;
        float* o0 = out + ((size_t)b * SEQ + row0) * DIM + h * DH;
        float* o1 = out + ((size_t)b * SEQ + row1) * DIM + h * DH;
#pragma unroll
        for (int nt = 0; nt < 8; nt++) {
            int c = nt * 8 + 2 * qq;
            *(float2*)(o0 + c) = make_float2(O[nt][0] * sc0, O[nt][1] * sc0);
            *(float2*)(o1 + c) = make_float2(O[nt][2] * sc1, O[nt][3] * sc1);
        }
    }
}

// ---------------------------------------------------------------------------
extern "C" void kernel_launch(void* const* d_in, const int* in_sizes, int n_in,
                              void* d_out, int out_size) {
    const float* x    = (const float*)d_in[0];
    const float* w    = (const float*)d_in[1];
    const float* bq   = (const float*)d_in[2];
    const float* dsc  = (const float*)d_in[3];
    const float* bias = (const float*)d_in[4];
    float* out = (float*)d_out;

    cudaFuncSetAttribute(attn_kernel, cudaFuncAttributeMaxDynamicSharedMemorySize, AT_SMEM);

    qkv_gemm<<<dim3(18, 128), 256>>>(x, w, bq);
    attn_kernel<<<dim3(8, BHT), 256, AT_SMEM>>>(dsc, bias, out);
}

// round 4
// speedup vs baseline: 3.0342x; 1.1683x over previous
#include <cuda_runtime.h>
#include <stdint.h>
#include <math.h>

#define SEQ   1024
#define HEADS 12
#define BATCH 16
#define DH    64
#define DIM   768
#define BHT   (BATCH*HEADS)   // 192
#define LOG2E 1.4426950408889634f

// scratch for q,k,v in (which, b*h, s, c) layout
__device__ float g_qkv[3UL * BHT * SEQ * DH];

__device__ __forceinline__ unsigned f2tf(float f) {
    unsigned r;
    asm("cvt.rna.tf32.f32 %0, %1;" : "=r"(r) : "f"(f));
    return r;
}
__device__ __forceinline__ uint32_t s2u(const void* p) {
    return (uint32_t)__cvta_generic_to_shared(p);
}
__device__ __forceinline__ void ldsm4(unsigned r[4], uint32_t a) {
    asm volatile("ldmatrix.sync.aligned.m8n8.x4.shared.b16 {%0,%1,%2,%3}, [%4];"
                 : "=r"(r[0]), "=r"(r[1]), "=r"(r[2]), "=r"(r[3]) : "r"(a));
}
__device__ __forceinline__ void cvt4(unsigned r[4]) {
#pragma unroll
    for (int j = 0; j < 4; j++) r[j] = f2tf(__uint_as_float(r[j]));
}
__device__ __forceinline__ void mma_tf32(float c[4], const unsigned a[4], const unsigned b[2]) {
    asm volatile("mma.sync.aligned.m16n8k8.row.col.f32.tf32.tf32.f32 "
                 "{%0,%1,%2,%3}, {%4,%5,%6,%7}, {%8,%9}, {%0,%1,%2,%3};"
                 : "+f"(c[0]), "+f"(c[1]), "+f"(c[2]), "+f"(c[3])
                 : "r"(a[0]), "r"(a[1]), "r"(a[2]), "r"(a[3]),
                   "r"(b[0]), "r"(b[1]));
}
__device__ __forceinline__ void cp16(uint32_t s, const void* g) {
    asm volatile("cp.async.ca.shared.global [%0], [%1], 16;" :: "r"(s), "l"(g));
}

// ---------------------------------------------------------------------------
// Kernel 1: qkv = x @ w^T + b  (tf32, ldmatrix + cp.async double-buffer)
// C tile 128x128, BK=32, 8 warps, each warp 32x64.
// smem: raw fp32 staged; cvt.rna.tf32 applied on fragment regs after ldmatrix.
// ---------------------------------------------------------------------------
#define LDA 36
#define TILE_W (128 * LDA)                 // words per tile
#define QKV_SMEM (4 * TILE_W * 4)          // 2 bufs x (A,B) = 73728 B

__global__ __launch_bounds__(256) void qkv_gemm(const float* __restrict__ x,
                                                const float* __restrict__ w,
                                                const float* __restrict__ bq) {
    extern __shared__ unsigned qsm[];
    const uint32_t smb = s2u(qsm);

    const int tid  = threadIdx.x;
    const int warp = tid >> 5;
    const int lane = tid & 31;
    const int r0   = lane >> 2;
    const int qq   = lane & 3;
    const int g    = lane >> 3;
    const int lr   = lane & 7;
    const int m_w  = (warp >> 1) * 32;
    const int n_w  = (warp & 1) * 64;

    float C[2][8][4];
#pragma unroll
    for (int i = 0; i < 2; i++)
#pragma unroll
        for (int j = 0; j < 8; j++)
#pragma unroll
            for (int k = 0; k < 4; k++) C[i][j][k] = 0.f;

    const float* Ag = x + (size_t)(blockIdx.y * 128) * DIM;
    const float* Bg = w + (size_t)(blockIdx.x * 128) * DIM;

    // cp.async load mapping: 4 rounds, each thread one 16B per array
    const int lr8 = tid >> 3;            // row base (0..31), +32 per round
    const int lc4 = (tid & 7) * 4;       // k-col group

    // ldmatrix fragment byte-offsets within a tile
    const uint32_t aoff = (uint32_t)(((m_w + (g & 1) * 8 + lr) * LDA + (g >> 1) * 4) * 4);
    const uint32_t boff = (uint32_t)(((n_w + (g >> 1) * 8 + lr) * LDA + (g & 1) * 4) * 4);

#define QKV_ISSUE(IT, BUF) do {                                                   \
    uint32_t ab = smb + (BUF) * (uint32_t)(TILE_W * 4);                           \
    uint32_t bb_ = smb + (uint32_t)(2 * TILE_W * 4) + (BUF) * (uint32_t)(TILE_W * 4); \
    _Pragma("unroll")                                                             \
    for (int i = 0; i < 4; i++) {                                                 \
        int r = lr8 + i * 32;                                                     \
        cp16(ab  + (uint32_t)((r * LDA + lc4) * 4), Ag + (size_t)r * DIM + (IT) * 32 + lc4); \
        cp16(bb_ + (uint32_t)((r * LDA + lc4) * 4), Bg + (size_t)r * DIM + (IT) * 32 + lc4); \
    } } while (0)

    QKV_ISSUE(0, 0);
    asm volatile("cp.async.commit_group;");
    QKV_ISSUE(1, 1);
    asm volatile("cp.async.commit_group;");

    for (int it = 0; it < 24; it++) {
        if (it < 23) asm volatile("cp.async.wait_group 1;");
        else         asm volatile("cp.async.wait_group 0;");
        __syncthreads();

        const uint32_t Ab = smb + (it & 1) * (uint32_t)(TILE_W * 4) + aoff;
        const uint32_t Bb = smb + (uint32_t)(2 * TILE_W * 4) + (it & 1) * (uint32_t)(TILE_W * 4) + boff;
#pragma unroll
        for (int ks = 0; ks < 4; ks++) {
            unsigned a[2][4];
#pragma unroll
            for (int mt = 0; mt < 2; mt++) {
                ldsm4(a[mt], Ab + mt * (uint32_t)(16 * LDA * 4) + ks * 32);
                cvt4(a[mt]);
            }
#pragma unroll
            for (int ntp = 0; ntp < 4; ntp++) {
                unsigned bf[4];
                ldsm4(bf, Bb + ntp * (uint32_t)(16 * LDA * 4) + ks * 32);
                cvt4(bf);
#pragma unroll
                for (int mt = 0; mt < 2; mt++) {
                    mma_tf32(C[mt][2 * ntp], a[mt], bf);
                    mma_tf32(C[mt][2 * ntp + 1], a[mt], bf + 2);
                }
            }
        }
        __syncthreads();
        if (it + 2 < 24) {
            QKV_ISSUE(it + 2, it & 1);
            asm volatile("cp.async.commit_group;");
        }
    }

    // epilogue: add bias, scatter into (which, bh, s, c)
#pragma unroll
    for (int nt = 0; nt < 8; nt++) {
        int nb = blockIdx.x * 128 + n_w + nt * 8 + 2 * qq;
        float2 bb = *(const float2*)(bq + nb);
        int which = nb / DIM;
        int hn    = nb % DIM;
        int h     = hn >> 6;
        int c0    = hn & 63;
        size_t base = ((size_t)which * BHT) * SEQ * DH + (size_t)h * SEQ * DH + c0;
#pragma unroll
        for (int mt = 0; mt < 2; mt++) {
            int m = blockIdx.y * 128 + m_w + mt * 16 + r0;
            {
                int b = m >> 10, s = m & 1023;
                float* dst = g_qkv + base + ((size_t)b * HEADS * SEQ + s) * DH;
                *(float2*)dst = make_float2(C[mt][nt][0] + bb.x, C[mt][nt][1] + bb.y);
            }
            {
                int m2 = m + 8;
                int b = m2 >> 10, s = m2 & 1023;
                float* dst = g_qkv + base + ((size_t)b * HEADS * SEQ + s) * DH;
                *(float2*)dst = make_float2(C[mt][nt][2] + bb.x, C[mt][nt][3] + bb.y);
            }
        }
    }
#undef QKV_ISSUE
}

// ---------------------------------------------------------------------------
// Kernel 2: flash attention, tf32 mma + ldmatrix everywhere.
// BM=128 rows/CTA, BN=64 keys/iter, 8 warps (16 rows each).
// Qs/Ks/Ps row-major stride 68 (tf32-converted); Vt stored transposed.
// ---------------------------------------------------------------------------
#define QS 68
#define AT_SMEM ((128 + 64 + 64 + 128) * QS * 4)   // 104448 B

__global__ __launch_bounds__(256) void attn_kernel(const float* __restrict__ dsc,
                                                   const float* __restrict__ bias,
                                                   float* __restrict__ out) {
    extern __shared__ unsigned smu[];
    unsigned* Qs = smu;               // [128][68] tf32
    unsigned* Ks = Qs + 128 * QS;     // [64][68]  tf32 (row=key, col=chan)
    unsigned* Vt = Ks + 64 * QS;      // [64][68]  tf32 TRANSPOSED (row=chan, col=key)
    unsigned* Ps = Vt + 64 * QS;      // [128][68] tf32

    const int tid  = threadIdx.x;
    const int warp = tid >> 5;
    const int lane = tid & 31;
    const int r0   = lane >> 2;
    const int qq   = lane & 3;
    const int g    = lane >> 3;
    const int lr   = lane & 7;
    const int wm   = warp * 16;

    const int bh = blockIdx.y;
    const int q0 = blockIdx.x * 128;
    const int b  = bh / HEADS;
    const int h  = bh % HEADS;

    const float* qp = g_qkv + ((size_t)(0 * BHT + bh) * SEQ + q0) * DH;
    const float* kp = g_qkv + ((size_t)(1 * BHT + bh) * SEQ) * DH;
    const float* vp = g_qkv + ((size_t)(2 * BHT + bh) * SEQ) * DH;

    // load Q tile (128x64) -> tf32 smem
#pragma unroll
    for (int i = 0; i < 8; i++) {
        int id = tid + i * 256;
        int r  = id >> 4;
        int c  = (id & 15) * 4;
        float4 a = *(const float4*)(qp + (size_t)r * DH + c);
        *(uint4*)&Qs[r * QS + c] = make_uint4(f2tf(a.x), f2tf(a.y), f2tf(a.z), f2tf(a.w));
    }

    // ldmatrix per-thread byte addresses
    const uint32_t smb = s2u(smu);
    const uint32_t Qb = smb;
    const uint32_t Kb = smb + 128 * QS * 4;
    const uint32_t Vb = Kb + 64 * QS * 4;
    const uint32_t Pb = Vb + 64 * QS * 4;
    const uint32_t qA = Qb + (uint32_t)(((wm + (g & 1) * 8 + lr) * QS + (g >> 1) * 4) * 4);
    const uint32_t pA = Pb + (uint32_t)(((wm + (g & 1) * 8 + lr) * QS + (g >> 1) * 4) * 4);
    const uint32_t kB = Kb + (uint32_t)((((g >> 1) * 8 + lr) * QS + (g & 1) * 4) * 4);
    const uint32_t vB = Vb + (uint32_t)((((g >> 1) * 8 + lr) * QS + (g & 1) * 4) * 4);

    float O[8][4];
#pragma unroll
    for (int i = 0; i < 8; i++)
#pragma unroll
        for (int j = 0; j < 4; j++) O[i][j] = 0.f;
    float m0 = -1e30f, m1 = -1e30f, l0 = 0.f, l1 = 0.f;

    const float scale = 0.125f * LOG2E;   // exp2 domain

    // V load mapping: lane-fastest over keys -> conflict-free transpose store
    const int vr = tid & 63;              // key index within tile

    for (int t = 0; t < 16; t++) {
        __syncthreads();
        // K tile (row-major) + V tile (transposed)
#pragma unroll
        for (int i = 0; i < 4; i++) {
            int id = tid + i * 256;
            int r  = id >> 4;
            int c  = (id & 15) * 4;
            float4 k4 = *(const float4*)(kp + (size_t)(t * 64 + r) * DH + c);
            *(uint4*)&Ks[r * QS + c] = make_uint4(f2tf(k4.x), f2tf(k4.y), f2tf(k4.z), f2tf(k4.w));
            int vc = ((id >> 6) & 15) * 4;
            float4 v4 = *(const float4*)(vp + (size_t)(t * 64 + vr) * DH + vc);
            Vt[(vc + 0) * QS + vr] = f2tf(v4.x);
            Vt[(vc + 1) * QS + vr] = f2tf(v4.y);
            Vt[(vc + 2) * QS + vr] = f2tf(v4.z);
            Vt[(vc + 3) * QS + vr] = f2tf(v4.w);
        }
        __syncthreads();

        // S = Q K^T
        float S[8][4];
#pragma unroll
        for (int i = 0; i < 8; i++)
#pragma unroll
            for (int j = 0; j < 4; j++) S[i][j] = 0.f;

#pragma unroll
        for (int ks = 0; ks < 8; ks++) {
            unsigned a[4];
            ldsm4(a, qA + ks * 32);
#pragma unroll
            for (int ntp = 0; ntp < 4; ntp++) {
                unsigned bf[4];
                ldsm4(bf, kB + ntp * (uint32_t)(16 * QS * 4) + ks * 32);
                mma_tf32(S[2 * ntp], a, bf);
                mma_tf32(S[2 * ntp + 1], a, bf + 2);
            }
        }

        // scale + bias (log2 domain), online softmax
        const float* br0 = bias + (size_t)(q0 + wm + r0) * SEQ + t * 64;
        const float* br1 = br0 + 8 * SEQ;
        float mx0 = -1e30f, mx1 = -1e30f;
#pragma unroll
        for (int nt = 0; nt < 8; nt++) {
            float2 b0 = *(const float2*)(br0 + nt * 8 + 2 * qq);
            float2 b1 = *(const float2*)(br1 + nt * 8 + 2 * qq);
            S[nt][0] = S[nt][0] * scale + b0.x * LOG2E;
            S[nt][1] = S[nt][1] * scale + b0.y * LOG2E;
            S[nt][2] = S[nt][2] * scale + b1.x * LOG2E;
            S[nt][3] = S[nt][3] * scale + b1.y * LOG2E;
            mx0 = fmaxf(mx0, fmaxf(S[nt][0], S[nt][1]));
            mx1 = fmaxf(mx1, fmaxf(S[nt][2], S[nt][3]));
        }
        mx0 = fmaxf(mx0, __shfl_xor_sync(0xffffffffu, mx0, 1));
        mx0 = fmaxf(mx0, __shfl_xor_sync(0xffffffffu, mx0, 2));
        mx1 = fmaxf(mx1, __shfl_xor_sync(0xffffffffu, mx1, 1));
        mx1 = fmaxf(mx1, __shfl_xor_sync(0xffffffffu, mx1, 2));

        float mn0 = fmaxf(m0, mx0), mn1 = fmaxf(m1, mx1);
        float f0 = exp2f(m0 - mn0), f1 = exp2f(m1 - mn1);
        m0 = mn0; m1 = mn1;

        float rs0 = 0.f, rs1 = 0.f;
#pragma unroll
        for (int nt = 0; nt < 8; nt++) {
            float p0 = exp2f(S[nt][0] - mn0);
            float p1 = exp2f(S[nt][1] - mn0);
            float p2 = exp2f(S[nt][2] - mn1);
            float p3 = exp2f(S[nt][3] - mn1);
            rs0 += p0 + p1;
            rs1 += p2 + p3;
            *(uint2*)&Ps[(wm + r0) * QS + nt * 8 + 2 * qq]     = make_uint2(f2tf(p0), f2tf(p1));
            *(uint2*)&Ps[(wm + r0 + 8) * QS + nt * 8 + 2 * qq] = make_uint2(f2tf(p2), f2tf(p3));
        }
        rs0 += __shfl_xor_sync(0xffffffffu, rs0, 1);
        rs0 += __shfl_xor_sync(0xffffffffu, rs0, 2);
        rs1 += __shfl_xor_sync(0xffffffffu, rs1, 1);
        rs1 += __shfl_xor_sync(0xffffffffu, rs1, 2);
        l0 = l0 * f0 + rs0;
        l1 = l1 * f1 + rs1;

#pragma unroll
        for (int nt = 0; nt < 8; nt++) {
            O[nt][0] *= f0; O[nt][1] *= f0;
            O[nt][2] *= f1; O[nt][3] *= f1;
        }
        __syncwarp();

        // O += P @ V   (P rows warp-private, Vt transposed)
#pragma unroll
        for (int ks = 0; ks < 8; ks++) {
            unsigned a[4];
            ldsm4(a, pA + ks * 32);
#pragma unroll
            for (int ntp = 0; ntp < 4; ntp++) {
                unsigned bf[4];
                ldsm4(bf, vB + ntp * (uint32_t)(16 * QS * 4) + ks * 32);
                mma_tf32(O[2 * ntp], a, bf);
                mma_tf32(O[2 * ntp + 1], a, bf + 2);
            }
        }
    }

    // epilogue
    {
        int row0 = q0 + wm + r0;
        int row1 = row0 + 8;
        float sc0 = dsc[row0] / l0;
        float sc1 = dsc[row1] / l1;
        float* o0 = out + ((size_t)b * SEQ + row0) * DIM + h * DH;
        float* o1 = out + ((size_t)b * SEQ + row1) * DIM + h * DH;
#pragma unroll
        for (int nt = 0; nt < 8; nt++) {
            int c = nt * 8 + 2 * qq;
            *(float2*)(o0 + c) = make_float2(O[nt][0] * sc0, O[nt][1] * sc0);
            *(float2*)(o1 + c) = make_float2(O[nt][2] * sc1, O[nt][3] * sc1);
        }
    }
}

// ---------------------------------------------------------------------------
extern "C" void kernel_launch(void* const* d_in, const int* in_sizes, int n_in,
                              void* d_out, int out_size) {
    const float* x    = (const float*)d_in[0];
    const float* w    = (const float*)d_in[1];
    const float* bq   = (const float*)d_in[2];
    const float* dsc  = (const float*)d_in[3];
    const float* bias = (const float*)d_in[4];
    float* out = (float*)d_out;

    cudaFuncSetAttribute(qkv_gemm, cudaFuncAttributeMaxDynamicSharedMemorySize, QKV_SMEM);
    cudaFuncSetAttribute(attn_kernel, cudaFuncAttributeMaxDynamicSharedMemorySize, AT_SMEM);

    qkv_gemm<<<dim3(18, 128), 256, QKV_SMEM>>>(x, w, bq);
    attn_kernel<<<dim3(8, BHT), 256, AT_SMEM>>>(dsc, bias, out);
}

// round 5
// speedup vs baseline: 3.5828x; 1.1808x over previous
#include <cuda_runtime.h>
#include <stdint.h>
#include <math.h>

#define SEQ   1024
#define HEADS 12
#define BATCH 16
#define DH    64
#define DIM   768
#define BHT   (BATCH*HEADS)   // 192
#define LOG2E 1.4426950408889634f

// pre-converted operands + attention scratch (tf32 bits stored as unsigned)
__device__ unsigned g_x32[(size_t)BATCH*SEQ*DIM];    // 12.58M
__device__ unsigned g_w32[(size_t)3*DIM*DIM];        // 1.77M
__device__ float    g_bL2[(size_t)SEQ*SEQ];          // bias * log2e
__device__ unsigned g_q[(size_t)BHT*SEQ*DH];
__device__ unsigned g_k[(size_t)BHT*SEQ*DH];
__device__ unsigned g_v[(size_t)BHT*DH*SEQ];         // TRANSPOSED: [bh][chan][key]

__device__ __forceinline__ unsigned f2tf(float f) {
    unsigned r;
    asm("cvt.rna.tf32.f32 %0, %1;" : "=r"(r) : "f"(f));
    return r;
}
__device__ __forceinline__ float ex2(float x) {
    float r;
    asm("ex2.approx.f32 %0, %1;" : "=f"(r) : "f"(x));
    return r;
}
__device__ __forceinline__ uint32_t s2u(const void* p) {
    return (uint32_t)__cvta_generic_to_shared(p);
}
__device__ __forceinline__ void ldsm4(unsigned r[4], uint32_t a) {
    asm volatile("ldmatrix.sync.aligned.m8n8.x4.shared.b16 {%0,%1,%2,%3}, [%4];"
                 : "=r"(r[0]), "=r"(r[1]), "=r"(r[2]), "=r"(r[3]) : "r"(a));
}
__device__ __forceinline__ void mma_tf32(float c[4], const unsigned a[4], const unsigned b[2]) {
    asm volatile("mma.sync.aligned.m16n8k8.row.col.f32.tf32.tf32.f32 "
                 "{%0,%1,%2,%3}, {%4,%5,%6,%7}, {%8,%9}, {%0,%1,%2,%3};"
                 : "+f"(c[0]), "+f"(c[1]), "+f"(c[2]), "+f"(c[3])
                 : "r"(a[0]), "r"(a[1]), "r"(a[2]), "r"(a[3]),
                   "r"(b[0]), "r"(b[1]));
}
__device__ __forceinline__ void cp16(uint32_t s, const void* g) {
    asm volatile("cp.async.ca.shared.global [%0], [%1], 16;" :: "r"(s), "l"(g));
}

// ---------------------------------------------------------------------------
// Kernel 0: one-shot input conversion (x, w -> tf32; bias -> bias*log2e)
// ---------------------------------------------------------------------------
#define NX (BATCH*SEQ*DIM)        // 12582912
#define NW (3*DIM*DIM)            // 1769472
#define NB (SEQ*SEQ)              // 1048576
#define CVT_BLOCKS ((NX+NW+NB)/4/256)   // 15040

__global__ __launch_bounds__(256) void cvt_inputs(const float* __restrict__ x,
                                                  const float* __restrict__ w,
                                                  const float* __restrict__ bias) {
    size_t i = ((size_t)blockIdx.x * 256 + threadIdx.x) * 4;
    if (i < NX) {
        float4 v = *(const float4*)(x + i);
        *(uint4*)(g_x32 + i) = make_uint4(f2tf(v.x), f2tf(v.y), f2tf(v.z), f2tf(v.w));
    } else if (i < NX + NW) {
        size_t j = i - NX;
        float4 v = *(const float4*)(w + j);
        *(uint4*)(g_w32 + j) = make_uint4(f2tf(v.x), f2tf(v.y), f2tf(v.z), f2tf(v.w));
    } else {
        size_t j = i - NX - NW;
        float4 v = *(const float4*)(bias + j);
        *(float4*)(g_bL2 + j) = make_float4(v.x * LOG2E, v.y * LOG2E, v.z * LOG2E, v.w * LOG2E);
    }
}

// ---------------------------------------------------------------------------
// Kernel 1: qkv = x @ w^T + b  (tf32, pre-converted operands, cp.async pipe)
// C tile 128x128, BK=32, 8 warps, each warp 32x64. No cvt in hot loop.
// Epilogue: add bias, cvt->tf32, scatter q/k row-major and v TRANSPOSED.
// ---------------------------------------------------------------------------
#define LDA 36
#define TILE_W (128 * LDA)
#define QKV_SMEM (4 * TILE_W * 4)          // 73728 B

__global__ __launch_bounds__(256) void qkv_gemm(const float* __restrict__ bq) {
    extern __shared__ unsigned qsm[];
    const uint32_t smb = s2u(qsm);

    const int tid  = threadIdx.x;
    const int warp = tid >> 5;
    const int lane = tid & 31;
    const int r0   = lane >> 2;
    const int qq   = lane & 3;
    const int g    = lane >> 3;
    const int lr   = lane & 7;
    const int m_w  = (warp >> 1) * 32;
    const int n_w  = (warp & 1) * 64;

    float C[2][8][4];
#pragma unroll
    for (int i = 0; i < 2; i++)
#pragma unroll
        for (int j = 0; j < 8; j++)
#pragma unroll
            for (int k = 0; k < 4; k++) C[i][j][k] = 0.f;

    const unsigned* Ag = g_x32 + (size_t)(blockIdx.y * 128) * DIM;
    const unsigned* Bg = g_w32 + (size_t)(blockIdx.x * 128) * DIM;

    const int lr8 = tid >> 3;
    const int lc4 = (tid & 7) * 4;

    const uint32_t aoff = (uint32_t)(((m_w + (g & 1) * 8 + lr) * LDA + (g >> 1) * 4) * 4);
    const uint32_t boff = (uint32_t)(((n_w + (g >> 1) * 8 + lr) * LDA + (g & 1) * 4) * 4);

#define QKV_ISSUE(IT, BUF) do {                                                   \
    uint32_t ab = smb + (BUF) * (uint32_t)(TILE_W * 4);                           \
    uint32_t bb_ = smb + (uint32_t)(2 * TILE_W * 4) + (BUF) * (uint32_t)(TILE_W * 4); \
    _Pragma("unroll")                                                             \
    for (int i = 0; i < 4; i++) {                                                 \
        int r = lr8 + i * 32;                                                     \
        cp16(ab  + (uint32_t)((r * LDA + lc4) * 4), Ag + (size_t)r * DIM + (IT) * 32 + lc4); \
        cp16(bb_ + (uint32_t)((r * LDA + lc4) * 4), Bg + (size_t)r * DIM + (IT) * 32 + lc4); \
    } } while (0)

    QKV_ISSUE(0, 0);
    asm volatile("cp.async.commit_group;");
    QKV_ISSUE(1, 1);
    asm volatile("cp.async.commit_group;");

    for (int it = 0; it < 24; it++) {
        if (it < 23) asm volatile("cp.async.wait_group 1;");
        else         asm volatile("cp.async.wait_group 0;");
        __syncthreads();

        const uint32_t Ab = smb + (it & 1) * (uint32_t)(TILE_W * 4) + aoff;
        const uint32_t Bb = smb + (uint32_t)(2 * TILE_W * 4) + (it & 1) * (uint32_t)(TILE_W * 4) + boff;
#pragma unroll
        for (int ks = 0; ks < 4; ks++) {
            unsigned a[2][4];
#pragma unroll
            for (int mt = 0; mt < 2; mt++)
                ldsm4(a[mt], Ab + mt * (uint32_t)(16 * LDA * 4) + ks * 32);
#pragma unroll
            for (int ntp = 0; ntp < 4; ntp++) {
                unsigned bf[4];
                ldsm4(bf, Bb + ntp * (uint32_t)(16 * LDA * 4) + ks * 32);
#pragma unroll
                for (int mt = 0; mt < 2; mt++) {
                    mma_tf32(C[mt][2 * ntp], a[mt], bf);
                    mma_tf32(C[mt][2 * ntp + 1], a[mt], bf + 2);
                }
            }
        }
        __syncthreads();
        if (it + 2 < 24) {
            QKV_ISSUE(it + 2, it & 1);
            asm volatile("cp.async.commit_group;");
        }
    }

    // epilogue: bias add, tf32 round, scatter (q/k row-major, v transposed)
#pragma unroll
    for (int nt = 0; nt < 8; nt++) {
        int nb = blockIdx.x * 128 + n_w + nt * 8 + 2 * qq;
        float2 bb = *(const float2*)(bq + nb);
        int which = nb / DIM;
        int hn    = nb % DIM;
        int h     = hn >> 6;
        int c0    = hn & 63;
#pragma unroll
        for (int mt = 0; mt < 2; mt++) {
#pragma unroll
            for (int half = 0; half < 2; half++) {
                int m = blockIdx.y * 128 + m_w + mt * 16 + r0 + half * 8;
                int b = m >> 10, s = m & 1023;
                unsigned u0 = f2tf(C[mt][nt][2 * half + 0] + bb.x);
                unsigned u1 = f2tf(C[mt][nt][2 * half + 1] + bb.y);
                size_t bh = (size_t)(b * HEADS + h);
                if (which == 0) {
                    *(uint2*)(g_q + (bh * SEQ + s) * DH + c0) = make_uint2(u0, u1);
                } else if (which == 1) {
                    *(uint2*)(g_k + (bh * SEQ + s) * DH + c0) = make_uint2(u0, u1);
                } else {
                    size_t vb = bh * DH * SEQ;
                    g_v[vb + (size_t)c0 * SEQ + s]       = u0;
                    g_v[vb + (size_t)(c0 + 1) * SEQ + s] = u1;
                }
            }
        }
    }
#undef QKV_ISSUE
}

// ---------------------------------------------------------------------------
// Kernel 2: flash attention. BM=256 rows/CTA, BN=64 keys/iter, 8 warps
// (32 rows each, 2 m-tiles). Q fragments in registers; P kept in registers
// (A-fragments built by 4-lane shuffles); K/V triple-buffered via cp.async.
// ---------------------------------------------------------------------------
#define QS    68
#define TILEW (64 * QS)                    // words per tile buffer
#define AT_SMEM (6 * TILEW * 4)            // 104448 B (Q staging aliases tiles 0-3)

__global__ __launch_bounds__(256, 1) void attn_kernel(const float* __restrict__ dsc,
                                                      float* __restrict__ out) {
    extern __shared__ unsigned smu[];
    const uint32_t smb = s2u(smu);

    const int tid  = threadIdx.x;
    const int warp = tid >> 5;
    const int lane = tid & 31;
    const int r0   = lane >> 2;
    const int q    = lane & 3;
    const int g    = lane >> 3;
    const int lr   = lane & 7;
    const int wm   = warp * 32;

    const int bh = blockIdx.y;
    const int q0 = blockIdx.x * 256;
    const int b  = bh / HEADS;
    const int h  = bh % HEADS;

    const unsigned* qg = g_q + ((size_t)bh * SEQ + q0) * DH;
    const unsigned* kg = g_k + (size_t)bh * SEQ * DH;
    const unsigned* vg = g_v + (size_t)bh * DH * SEQ;

    // ---- stage Q tile (256x64) into smem, pull fragments into registers ----
#pragma unroll
    for (int i = 0; i < 16; i++) {
        int id = tid + i * 256;
        int r  = id >> 4;
        int c  = (id & 15) * 4;
        *(uint4*)&smu[r * QS + c] = *(const uint4*)(qg + (size_t)r * DH + c);
    }
    __syncthreads();

    unsigned Qf[2][8][4];
    {
        uint32_t qA = smb + (uint32_t)(((wm + (g & 1) * 8 + lr) * QS + (g >> 1) * 4) * 4);
#pragma unroll
        for (int mt = 0; mt < 2; mt++)
#pragma unroll
            for (int ks = 0; ks < 8; ks++)
                ldsm4(Qf[mt][ks], qA + mt * (uint32_t)(16 * QS * 4) + ks * 32);
    }
    __syncthreads();   // staging region becomes K/V buffers now

    // cp.async mapping: per thread 4 chunks per tile
    const int cr  = tid >> 4;        // row 0..15 (+16 per round)
    const int cc  = (tid & 15) * 4;  // word col

#define AT_ISSUE(T, J) do {                                                       \
    uint32_t kb = smb + (uint32_t)((2 * (J)) * TILEW * 4);                        \
    uint32_t vb = smb + (uint32_t)((2 * (J) + 1) * TILEW * 4);                    \
    _Pragma("unroll")                                                             \
    for (int i = 0; i < 4; i++) {                                                 \
        int r = cr + i * 16;                                                      \
        cp16(kb + (uint32_t)((r * QS + cc) * 4), kg + (size_t)((T) * 64 + r) * DH + cc); \
        cp16(vb + (uint32_t)((r * QS + cc) * 4), vg + (size_t)r * SEQ + (T) * 64 + cc);  \
    } } while (0)

    AT_ISSUE(0, 0);
    asm volatile("cp.async.commit_group;");
    AT_ISSUE(1, 1);
    asm volatile("cp.async.commit_group;");

    float O[2][8][4];
#pragma unroll
    for (int mt = 0; mt < 2; mt++)
#pragma unroll
        for (int nt = 0; nt < 8; nt++)
#pragma unroll
            for (int k = 0; k < 4; k++) O[mt][nt][k] = 0.f;
    float mrow[4] = {-1e30f, -1e30f, -1e30f, -1e30f};  // [mt*2 + hi]
    float lrow[4] = {0.f, 0.f, 0.f, 0.f};

    const float scale = 0.125f * LOG2E;
    const unsigned srcA = (lane & ~3u) | ((unsigned)q >> 1);
    const unsigned srcB = srcA | 2u;

    const uint32_t fragoff = (uint32_t)((((g >> 1) * 8 + lr) * QS + (g & 1) * 4) * 4);

    for (int t = 0; t < 16; t++) {
        if (t < 15) asm volatile("cp.async.wait_group 1;");
        else        asm volatile("cp.async.wait_group 0;");
        __syncthreads();
        if (t + 2 < 16) {
            AT_ISSUE(t + 2, (t + 2) % 3);
            asm volatile("cp.async.commit_group;");
        }
        const int j = t % 3;
        const uint32_t kB = smb + (uint32_t)((2 * j) * TILEW * 4) + fragoff;
        const uint32_t vB = smb + (uint32_t)((2 * j + 1) * TILEW * 4) + fragoff;

        // ---- S = Q K^T  (per warp: 32 x 64) ----
        float S[2][8][4];
#pragma unroll
        for (int mt = 0; mt < 2; mt++)
#pragma unroll
            for (int nt = 0; nt < 8; nt++)
#pragma unroll
                for (int k = 0; k < 4; k++) S[mt][nt][k] = 0.f;

#pragma unroll
        for (int ks = 0; ks < 8; ks++) {
#pragma unroll
            for (int ntp = 0; ntp < 4; ntp++) {
                unsigned bf[4];
                ldsm4(bf, kB + ntp * (uint32_t)(16 * QS * 4) + ks * 32);
#pragma unroll
                for (int mt = 0; mt < 2; mt++) {
                    mma_tf32(S[mt][2 * ntp], Qf[mt][ks], bf);
                    mma_tf32(S[mt][2 * ntp + 1], Qf[mt][ks], bf + 2);
                }
            }
        }

        // ---- scale + bias (log2 domain), online softmax ----
#pragma unroll
        for (int mt = 0; mt < 2; mt++) {
            const float* b_lo = g_bL2 + (size_t)(q0 + wm + mt * 16 + r0) * SEQ + t * 64;
            const float* b_hi = b_lo + 8 * SEQ;
            float mlo = -1e30f, mhi = -1e30f;
#pragma unroll
            for (int nt = 0; nt < 8; nt++) {
                float2 bb0 = *(const float2*)(b_lo + nt * 8 + 2 * q);
                float2 bb1 = *(const float2*)(b_hi + nt * 8 + 2 * q);
                S[mt][nt][0] = S[mt][nt][0] * scale + bb0.x;
                S[mt][nt][1] = S[mt][nt][1] * scale + bb0.y;
                S[mt][nt][2] = S[mt][nt][2] * scale + bb1.x;
                S[mt][nt][3] = S[mt][nt][3] * scale + bb1.y;
                mlo = fmaxf(mlo, fmaxf(S[mt][nt][0], S[mt][nt][1]));
                mhi = fmaxf(mhi, fmaxf(S[mt][nt][2], S[mt][nt][3]));
            }
            mlo = fmaxf(mlo, __shfl_xor_sync(0xffffffffu, mlo, 1));
            mlo = fmaxf(mlo, __shfl_xor_sync(0xffffffffu, mlo, 2));
            mhi = fmaxf(mhi, __shfl_xor_sync(0xffffffffu, mhi, 1));
            mhi = fmaxf(mhi, __shfl_xor_sync(0xffffffffu, mhi, 2));

            float mn_lo = fmaxf(mrow[mt * 2 + 0], mlo);
            float mn_hi = fmaxf(mrow[mt * 2 + 1], mhi);
            float f_lo  = ex2(mrow[mt * 2 + 0] - mn_lo);
            float f_hi  = ex2(mrow[mt * 2 + 1] - mn_hi);
            mrow[mt * 2 + 0] = mn_lo;
            mrow[mt * 2 + 1] = mn_hi;

            float rlo = 0.f, rhi = 0.f;
#pragma unroll
            for (int nt = 0; nt < 8; nt++) {
                S[mt][nt][0] = ex2(S[mt][nt][0] - mn_lo);
                S[mt][nt][1] = ex2(S[mt][nt][1] - mn_lo);
                S[mt][nt][2] = ex2(S[mt][nt][2] - mn_hi);
                S[mt][nt][3] = ex2(S[mt][nt][3] - mn_hi);
                rlo += S[mt][nt][0] + S[mt][nt][1];
                rhi += S[mt][nt][2] + S[mt][nt][3];
            }
            rlo += __shfl_xor_sync(0xffffffffu, rlo, 1);
            rlo += __shfl_xor_sync(0xffffffffu, rlo, 2);
            rhi += __shfl_xor_sync(0xffffffffu, rhi, 1);
            rhi += __shfl_xor_sync(0xffffffffu, rhi, 2);
            lrow[mt * 2 + 0] = lrow[mt * 2 + 0] * f_lo + rlo;
            lrow[mt * 2 + 1] = lrow[mt * 2 + 1] * f_hi + rhi;

#pragma unroll
            for (int nt = 0; nt < 8; nt++) {
                O[mt][nt][0] *= f_lo; O[mt][nt][1] *= f_lo;
                O[mt][nt][2] *= f_hi; O[mt][nt][3] *= f_hi;
            }
        }

        // ---- O += P @ V ; P A-fragments via 4-lane shuffles of S regs ----
#pragma unroll
        for (int ks = 0; ks < 8; ks++) {
            unsigned aP[2][4];
#pragma unroll
            for (int mt = 0; mt < 2; mt++) {
                float s0 = S[mt][ks][0], s1 = S[mt][ks][1];
                float s2 = S[mt][ks][2], s3 = S[mt][ks][3];
                float v0a = __shfl_sync(0xffffffffu, s0, srcA);
                float v1a = __shfl_sync(0xffffffffu, s1, srcA);
                float v2a = __shfl_sync(0xffffffffu, s2, srcA);
                float v3a = __shfl_sync(0xffffffffu, s3, srcA);
                float v0b = __shfl_sync(0xffffffffu, s0, srcB);
                float v1b = __shfl_sync(0xffffffffu, s1, srcB);
                float v2b = __shfl_sync(0xffffffffu, s2, srcB);
                float v3b = __shfl_sync(0xffffffffu, s3, srcB);
                bool odd = (q & 1);
                aP[mt][0] = f2tf(odd ? v1a : v0a);   // (r0,   q)
                aP[mt][1] = f2tf(odd ? v3a : v2a);   // (r0+8, q)
                aP[mt][2] = f2tf(odd ? v1b : v0b);   // (r0,   q+4)
                aP[mt][3] = f2tf(odd ? v3b : v2b);   // (r0+8, q+4)
            }
#pragma unroll
            for (int ntp = 0; ntp < 4; ntp++) {
                unsigned bf[4];
                ldsm4(bf, vB + ntp * (uint32_t)(16 * QS * 4) + ks * 32);
#pragma unroll
                for (int mt = 0; mt < 2; mt++) {
                    mma_tf32(O[mt][2 * ntp], aP[mt], bf);
                    mma_tf32(O[mt][2 * ntp + 1], aP[mt], bf + 2);
                }
            }
        }
    }

    // ---- epilogue: out[b, row, h*64 + c] = d[row]/l * O ----
#pragma unroll
    for (int mt = 0; mt < 2; mt++) {
        int row_lo = q0 + wm + mt * 16 + r0;
        int row_hi = row_lo + 8;
        float sc_lo = dsc[row_lo] / lrow[mt * 2 + 0];
        float sc_hi = dsc[row_hi] / lrow[mt * 2 + 1];
        float* o_lo = out + ((size_t)b * SEQ + row_lo) * DIM + h * DH;
        float* o_hi = out + ((size_t)b * SEQ + row_hi) * DIM + h * DH;
#pragma unroll
        for (int nt = 0; nt < 8; nt++) {
            int c = nt * 8 + 2 * q;
            *(float2*)(o_lo + c) = make_float2(O[mt][nt][0] * sc_lo, O[mt][nt][1] * sc_lo);
            *(float2*)(o_hi + c) = make_float2(O[mt][nt][2] * sc_hi, O[mt][nt][3] * sc_hi);
        }
    }
#undef AT_ISSUE
}

// ---------------------------------------------------------------------------
extern "C" void kernel_launch(void* const* d_in, const int* in_sizes, int n_in,
                              void* d_out, int out_size) {
    const float* x    = (const float*)d_in[0];
    const float* w    = (const float*)d_in[1];
    const float* bq   = (const float*)d_in[2];
    const float* dsc  = (const float*)d_in[3];
    const float* bias = (const float*)d_in[4];
    float* out = (float*)d_out;

    cudaFuncSetAttribute(qkv_gemm, cudaFuncAttributeMaxDynamicSharedMemorySize, QKV_SMEM);
    cudaFuncSetAttribute(attn_kernel, cudaFuncAttributeMaxDynamicSharedMemorySize, AT_SMEM);

    cvt_inputs<<<CVT_BLOCKS, 256>>>(x, w, bias);
    qkv_gemm<<<dim3(18, 128), 256, QKV_SMEM>>>(bq);
    attn_kernel<<<dim3(4, BHT), 256, AT_SMEM>>>(dsc, out);
}